// round 13
// baseline (speedup 1.0000x reference)
#include <cuda_runtime.h>

// SpikingLayer: input (B*T, 32*32*32) f32, B=16, T=128.
// Per (b, feat): state = max(syn_t + state - act, -1); act = s>0 ? floor(s) : 0.
//
// FINAL KERNEL — verified twice at 78.6us kernel / 88.6us bench.
// Pure HBM stream: 268MB in + 268MB out, pinned at the B300 mixed-R/W DRAM
// ceiling (~6.12 TB/s = 77% of 8TB/s spec, bus-turnaround limited). Eleven
// benched variants confirmed invariance to: CTA shape, pipeline depth (2/4/6),
// store batching, occupancy (20%/41%/81% -> identical bandwidth), access width
// (64/128/256-bit), and store policy. Both streams are compulsory: the scalar
// time recurrence is nonlinear (floor+clamp -> no scan reformulation) and the
// f32 output is fixed by the harness contract.
//
// Config: 1024 CTAs x 128 threads, one thread per float4 column, 4-deep
// software-pipelined prefetch (8 LDG.128 in flight/thread), .cs streaming
// loads, .wt write-through stores (output never re-read; avoids lazy-
// writeback interleave against demand reads at the DRAM banks).

#define T_STEPS 128
#define FEAT    32768            // 32*32*32
#define F4      (FEAT / 4)       // 8192 float4 per time step
#define BATCH   16

__global__ __launch_bounds__(128, 8)
void spiking_layer_kernel(const float4* __restrict__ x, float4* __restrict__ out) {
    const unsigned tid = blockIdx.x * blockDim.x + threadIdx.x;  // 0 .. 131071
    const unsigned b = tid >> 13;        // / 8192
    const unsigned f = tid & (F4 - 1);   // % 8192

    const size_t base = (size_t)b * T_STEPS * F4 + f;
    const float4* __restrict__ in = x + base;
    float4* __restrict__ o = out + base;

    float sx = 0.f, sy = 0.f, sz = 0.f, sw = 0.f;   // membrane state
    float ax = 0.f, ay = 0.f, az = 0.f, aw = 0.f;   // last activation

    #define STEP_STORE(v, t_idx)                                          \
        sx = fmaxf(v.x + sx - ax, -1.0f);                                 \
        sy = fmaxf(v.y + sy - ay, -1.0f);                                 \
        sz = fmaxf(v.z + sz - az, -1.0f);                                 \
        sw = fmaxf(v.w + sw - aw, -1.0f);                                 \
        ax = (sx > 0.f) ? floorf(sx) : 0.f;                               \
        ay = (sy > 0.f) ? floorf(sy) : 0.f;                               \
        az = (sz > 0.f) ? floorf(sz) : 0.f;                               \
        aw = (sw > 0.f) ? floorf(sw) : 0.f;                               \
        __stwt(o + (size_t)(t_idx) * F4, make_float4(ax, ay, az, aw));

    // Prologue: load chunk 0 (t = 0..3)
    float4 c0 = __ldcs(in + 0 * (size_t)F4);
    float4 c1 = __ldcs(in + 1 * (size_t)F4);
    float4 c2 = __ldcs(in + 2 * (size_t)F4);
    float4 c3 = __ldcs(in + 3 * (size_t)F4);

    #pragma unroll 1
    for (int t = 0; t < T_STEPS - 4; t += 4) {
        // Prefetch next chunk before touching current one (keeps 8 loads in flight)
        float4 n0 = __ldcs(in + (size_t)(t + 4) * F4);
        float4 n1 = __ldcs(in + (size_t)(t + 5) * F4);
        float4 n2 = __ldcs(in + (size_t)(t + 6) * F4);
        float4 n3 = __ldcs(in + (size_t)(t + 7) * F4);

        STEP_STORE(c0, t + 0);
        STEP_STORE(c1, t + 1);
        STEP_STORE(c2, t + 2);
        STEP_STORE(c3, t + 3);

        c0 = n0; c1 = n1; c2 = n2; c3 = n3;
    }

    // Epilogue: t = 124..127
    STEP_STORE(c0, T_STEPS - 4);
    STEP_STORE(c1, T_STEPS - 3);
    STEP_STORE(c2, T_STEPS - 2);
    STEP_STORE(c3, T_STEPS - 1);

    #undef STEP_STORE
}

extern "C" void kernel_launch(void* const* d_in, const int* in_sizes, int n_in,
                              void* d_out, int out_size) {
    const float4* x = (const float4*)d_in[0];
    float4* o = (float4*)d_out;
    const int total_threads = BATCH * F4;          // 131072
    spiking_layer_kernel<<<total_threads / 128, 128>>>(x, o);
}

// round 14
// speedup vs baseline: 1.0025x; 1.0025x over previous
#include <cuda_runtime.h>

// SpikingLayer: input (B*T, 32*32*32) f32, B=16, T=128.
// Per (b, feat): state = max(syn_t + state - act, -1); act = s>0 ? floor(s) : 0.
//
// FINAL KERNEL — bench-verified three times: 88.58us (bit-identical on the
// last two runs). Pure HBM stream: 268MB in + 268MB out, pinned at the B300
// mixed-R/W DRAM ceiling (~6.1 TB/s = 77% of 8TB/s spec, bus-turnaround
// limited). Eleven benched variants confirmed invariance to: CTA shape,
// pipeline depth (2/4/6), store batching, occupancy (20%/41%/81% -> identical
// bandwidth), access width (64/128/256-bit), and store policy. Both streams
// are compulsory: the scalar time recurrence is nonlinear (floor+clamp -> no
// scan reformulation) and the f32 output is fixed by the harness contract.
//
// Config: 1024 CTAs x 128 threads, one thread per float4 column, 4-deep
// software-pipelined prefetch (8 LDG.128 in flight/thread), .cs streaming
// loads, .wt write-through stores (output never re-read; avoids lazy-
// writeback interleave against demand reads at the DRAM banks).

#define T_STEPS 128
#define FEAT    32768            // 32*32*32
#define F4      (FEAT / 4)       // 8192 float4 per time step
#define BATCH   16

__global__ __launch_bounds__(128, 8)
void spiking_layer_kernel(const float4* __restrict__ x, float4* __restrict__ out) {
    const unsigned tid = blockIdx.x * blockDim.x + threadIdx.x;  // 0 .. 131071
    const unsigned b = tid >> 13;        // / 8192
    const unsigned f = tid & (F4 - 1);   // % 8192

    const size_t base = (size_t)b * T_STEPS * F4 + f;
    const float4* __restrict__ in = x + base;
    float4* __restrict__ o = out + base;

    float sx = 0.f, sy = 0.f, sz = 0.f, sw = 0.f;   // membrane state
    float ax = 0.f, ay = 0.f, az = 0.f, aw = 0.f;   // last activation

    #define STEP_STORE(v, t_idx)                                          \
        sx = fmaxf(v.x + sx - ax, -1.0f);                                 \
        sy = fmaxf(v.y + sy - ay, -1.0f);                                 \
        sz = fmaxf(v.z + sz - az, -1.0f);                                 \
        sw = fmaxf(v.w + sw - aw, -1.0f);                                 \
        ax = (sx > 0.f) ? floorf(sx) : 0.f;                               \
        ay = (sy > 0.f) ? floorf(sy) : 0.f;                               \
        az = (sz > 0.f) ? floorf(sz) : 0.f;                               \
        aw = (sw > 0.f) ? floorf(sw) : 0.f;                               \
        __stwt(o + (size_t)(t_idx) * F4, make_float4(ax, ay, az, aw));

    // Prologue: load chunk 0 (t = 0..3)
    float4 c0 = __ldcs(in + 0 * (size_t)F4);
    float4 c1 = __ldcs(in + 1 * (size_t)F4);
    float4 c2 = __ldcs(in + 2 * (size_t)F4);
    float4 c3 = __ldcs(in + 3 * (size_t)F4);

    #pragma unroll 1
    for (int t = 0; t < T_STEPS - 4; t += 4) {
        // Prefetch next chunk before touching current one (keeps 8 loads in flight)
        float4 n0 = __ldcs(in + (size_t)(t + 4) * F4);
        float4 n1 = __ldcs(in + (size_t)(t + 5) * F4);
        float4 n2 = __ldcs(in + (size_t)(t + 6) * F4);
        float4 n3 = __ldcs(in + (size_t)(t + 7) * F4);

        STEP_STORE(c0, t + 0);
        STEP_STORE(c1, t + 1);
        STEP_STORE(c2, t + 2);
        STEP_STORE(c3, t + 3);

        c0 = n0; c1 = n1; c2 = n2; c3 = n3;
    }

    // Epilogue: t = 124..127
    STEP_STORE(c0, T_STEPS - 4);
    STEP_STORE(c1, T_STEPS - 3);
    STEP_STORE(c2, T_STEPS - 2);
    STEP_STORE(c3, T_STEPS - 1);

    #undef STEP_STORE
}

extern "C" void kernel_launch(void* const* d_in, const int* in_sizes, int n_in,
                              void* d_out, int out_size) {
    const float4* x = (const float4*)d_in[0];
    float4* o = (float4*)d_out;
    const int total_threads = BATCH * F4;          // 131072
    spiking_layer_kernel<<<total_threads / 128, 128>>>(x, o);
}

// round 15
// speedup vs baseline: 1.0040x; 1.0015x over previous
#include <cuda_runtime.h>

// SpikingLayer: input (B*T, 32*32*32) f32, B=16, T=128.
// Per (b, feat): state = max(syn_t + state - act, -1); act = s>0 ? floor(s) : 0.
//
// FINAL KERNEL — bench-verified four times: 88.61/88.58/88.58/88.35us
// (sigma ~0.1us). Pure HBM stream: 268MB in + 268MB out, pinned at the B300
// mixed-R/W DRAM ceiling (~6.1 TB/s = 77% of 8TB/s spec, bus-turnaround
// limited). Eleven benched variants confirmed invariance to: CTA shape,
// pipeline depth (2/4/6), store batching, occupancy (20%/41%/81% -> identical
// bandwidth), access width (64/128/256-bit), and store policy. Both streams
// are compulsory: the scalar time recurrence is nonlinear (floor+clamp -> no
// scan reformulation) and the f32 output is fixed by the harness contract.
//
// Config: 1024 CTAs x 128 threads, one thread per float4 column, 4-deep
// software-pipelined prefetch (8 LDG.128 in flight/thread), .cs streaming
// loads, .wt write-through stores (output never re-read; avoids lazy-
// writeback interleave against demand reads at the DRAM banks).

#define T_STEPS 128
#define FEAT    32768            // 32*32*32
#define F4      (FEAT / 4)       // 8192 float4 per time step
#define BATCH   16

__global__ __launch_bounds__(128, 8)
void spiking_layer_kernel(const float4* __restrict__ x, float4* __restrict__ out) {
    const unsigned tid = blockIdx.x * blockDim.x + threadIdx.x;  // 0 .. 131071
    const unsigned b = tid >> 13;        // / 8192
    const unsigned f = tid & (F4 - 1);   // % 8192

    const size_t base = (size_t)b * T_STEPS * F4 + f;
    const float4* __restrict__ in = x + base;
    float4* __restrict__ o = out + base;

    float sx = 0.f, sy = 0.f, sz = 0.f, sw = 0.f;   // membrane state
    float ax = 0.f, ay = 0.f, az = 0.f, aw = 0.f;   // last activation

    #define STEP_STORE(v, t_idx)                                          \
        sx = fmaxf(v.x + sx - ax, -1.0f);                                 \
        sy = fmaxf(v.y + sy - ay, -1.0f);                                 \
        sz = fmaxf(v.z + sz - az, -1.0f);                                 \
        sw = fmaxf(v.w + sw - aw, -1.0f);                                 \
        ax = (sx > 0.f) ? floorf(sx) : 0.f;                               \
        ay = (sy > 0.f) ? floorf(sy) : 0.f;                               \
        az = (sz > 0.f) ? floorf(sz) : 0.f;                               \
        aw = (sw > 0.f) ? floorf(sw) : 0.f;                               \
        __stwt(o + (size_t)(t_idx) * F4, make_float4(ax, ay, az, aw));

    // Prologue: load chunk 0 (t = 0..3)
    float4 c0 = __ldcs(in + 0 * (size_t)F4);
    float4 c1 = __ldcs(in + 1 * (size_t)F4);
    float4 c2 = __ldcs(in + 2 * (size_t)F4);
    float4 c3 = __ldcs(in + 3 * (size_t)F4);

    #pragma unroll 1
    for (int t = 0; t < T_STEPS - 4; t += 4) {
        // Prefetch next chunk before touching current one (keeps 8 loads in flight)
        float4 n0 = __ldcs(in + (size_t)(t + 4) * F4);
        float4 n1 = __ldcs(in + (size_t)(t + 5) * F4);
        float4 n2 = __ldcs(in + (size_t)(t + 6) * F4);
        float4 n3 = __ldcs(in + (size_t)(t + 7) * F4);

        STEP_STORE(c0, t + 0);
        STEP_STORE(c1, t + 1);
        STEP_STORE(c2, t + 2);
        STEP_STORE(c3, t + 3);

        c0 = n0; c1 = n1; c2 = n2; c3 = n3;
    }

    // Epilogue: t = 124..127
    STEP_STORE(c0, T_STEPS - 4);
    STEP_STORE(c1, T_STEPS - 3);
    STEP_STORE(c2, T_STEPS - 2);
    STEP_STORE(c3, T_STEPS - 1);

    #undef STEP_STORE
}

extern "C" void kernel_launch(void* const* d_in, const int* in_sizes, int n_in,
                              void* d_out, int out_size) {
    const float4* x = (const float4*)d_in[0];
    float4* o = (float4*)d_out;
    const int total_threads = BATCH * F4;          // 131072
    spiking_layer_kernel<<<total_threads / 128, 128>>>(x, o);
}